// round 6
// baseline (speedup 1.0000x reference)
#include <cuda_runtime.h>

// Problem constants
#define NN 50000
#define EE 800000
#define NH 64
#define NGR 500
#define MAXD 96   // adjacency slot stride (Poisson(16) max-degree bound w/ huge margin)

// Scratch (device globals; no allocation allowed)
__device__ __align__(16) float g_X[NN * NH];
__device__ __align__(16) float g_Y[NN * NH];
__device__ __align__(16) float g_hWp[NN * NH];   // (X @ conv_W) * dinv[row]
__device__ __align__(16) float g_base[NN * NH];  // X @ res_W + conv_b + res_b
__device__ int g_cnt[NN];
__device__ int g_adj[NN * MAXD];

// ---------------------------------------------------------------------------
// Zero counters + output
// ---------------------------------------------------------------------------
__global__ void k_zero(float* __restrict__ out) {
    int i = blockIdx.x * 256 + threadIdx.x;
    if (i < NN) g_cnt[i] = 0;
    if (i < NGR) out[i] = 0.0f;
}

// ---------------------------------------------------------------------------
// Build fixed-stride adjacency (incoming edges per dst) + in-degree counts
// ---------------------------------------------------------------------------
__global__ void k_build(const int* __restrict__ ei) {
    int e = blockIdx.x * 256 + threadIdx.x;
    if (e >= EE) return;
    int s = ei[e];
    int d = ei[EE + e];
    int pos = atomicAdd(&g_cnt[d], 1);
    if (pos < MAXD) g_adj[d * MAXD + pos] = s;
}

// ---------------------------------------------------------------------------
// Encoder: Y = X = concat(x, pos) @ enc_W + enc_b
// ---------------------------------------------------------------------------
__global__ void k_encoder(const float* __restrict__ x, const float* __restrict__ pos,
                          const float* __restrict__ encW, const float* __restrict__ encB) {
    __shared__ float Ws[16 * 64];
    int t = threadIdx.x;  // 256
    for (int i = t; i < 16 * 64; i += 256) Ws[i] = encW[i];
    __syncthreads();
    int c = t & 63;
    int n = blockIdx.x * 4 + (t >> 6);
    if (n >= NN) return;
    float acc = 0.0f;
#pragma unroll
    for (int f = 0; f < 14; f++) acc += x[n * 14 + f] * Ws[f * 64 + c];
    acc += pos[n * 2 + 0] * Ws[14 * 64 + c];
    acc += pos[n * 2 + 1] * Ws[15 * 64 + c];
    acc += encB[c];
    g_Y[n * 64 + c] = acc;
    g_X[n * 64 + c] = acc;
}

// ---------------------------------------------------------------------------
// Dual GEMM, 64-row blocks, 256 threads (16x16), 4x4 register tiles:
//   hW'  = (X @ conv_W) * dinv[row]
//   base =  X @ res_W + conv_b + res_b
// ---------------------------------------------------------------------------
__global__ void k_layer_gemm(const float* __restrict__ convW, const float* __restrict__ convB,
                             const float* __restrict__ resW, const float* __restrict__ resB) {
    __shared__ float Xs[64][64];  // [row][k]
    __shared__ float Wc[64][64];  // [k][col]
    __shared__ float Wr[64][64];
    int t = threadIdx.x;  // 256
    int row0 = blockIdx.x * 64;
    for (int i = t; i < 4096; i += 256) {
        Wc[i >> 6][i & 63] = convW[i];
        Wr[i >> 6][i & 63] = resW[i];
    }
    for (int i = t; i < 4096; i += 256) {
        int r = i >> 6, k = i & 63;
        int n = row0 + r;
        if (n >= NN) n = NN - 1;  // clamp; stores guarded
        Xs[r][k] = g_X[n * 64 + k];
    }
    __syncthreads();

    int tx = t & 15, ty = t >> 4;
    int c0 = tx * 4, r0 = ty * 4;
    float accC[4][4], accR[4][4];
#pragma unroll
    for (int i = 0; i < 4; i++)
#pragma unroll
        for (int j = 0; j < 4; j++) { accC[i][j] = 0.0f; accR[i][j] = 0.0f; }

#pragma unroll 16
    for (int k = 0; k < 64; k++) {
        float a[4], wc[4], wr[4];
#pragma unroll
        for (int i = 0; i < 4; i++) a[i] = Xs[r0 + i][k];
#pragma unroll
        for (int j = 0; j < 4; j++) { wc[j] = Wc[k][c0 + j]; wr[j] = Wr[k][c0 + j]; }
#pragma unroll
        for (int i = 0; i < 4; i++)
#pragma unroll
            for (int j = 0; j < 4; j++) {
                accC[i][j] += a[i] * wc[j];
                accR[i][j] += a[i] * wr[j];
            }
    }

    float bc[4];
#pragma unroll
    for (int j = 0; j < 4; j++) bc[j] = convB[c0 + j] + resB[c0 + j];

#pragma unroll
    for (int i = 0; i < 4; i++) {
        int n = row0 + r0 + i;
        if (n < NN) {
            float dv = rsqrtf((float)g_cnt[n] + 1.0f);
            float4 h = make_float4(accC[i][0] * dv, accC[i][1] * dv,
                                   accC[i][2] * dv, accC[i][3] * dv);
            float4 b = make_float4(accR[i][0] + bc[0], accR[i][1] + bc[1],
                                   accR[i][2] + bc[2], accR[i][3] + bc[3]);
            *(float4*)&g_hWp[n * 64 + c0] = h;
            *(float4*)&g_base[n * 64 + c0] = b;
        }
    }
}

// ---------------------------------------------------------------------------
// Gather-aggregate + fused GraphCON update. One warp per node, float2/lane.
//   agg = dinv[n] * (sum_{incoming} hW'[src] + hW'[n]) + base[n]
//   Ynew = relu(agg) - X ;  (since Y + (relu - Y - X))
//   X   += Ynew
// ---------------------------------------------------------------------------
__global__ void k_agg_update() {
    int t = threadIdx.x;  // 256 = 8 warps
    int lane = t & 31;
    int n = blockIdx.x * 8 + (t >> 5);
    if (n >= NN) return;

    int deg = g_cnt[n];
    if (deg > MAXD) deg = MAXD;
    const float2* __restrict__ hw2 = (const float2*)g_hWp;

    float2 acc = hw2[n * 32 + lane];  // self-loop term
    const int* __restrict__ row = &g_adj[n * MAXD];
    for (int b = 0; b < deg; b += 32) {
        int id = (b + lane < deg) ? row[b + lane] : 0;
        int cnt = deg - b; if (cnt > 32) cnt = 32;
        for (int i = 0; i < cnt; i++) {
            int s = __shfl_sync(0xffffffffu, id, i);
            float2 v = hw2[s * 32 + lane];
            acc.x += v.x; acc.y += v.y;
        }
    }

    float dv = rsqrtf((float)g_cnt[n] + 1.0f);
    float2 base = ((const float2*)g_base)[n * 32 + lane];
    float ax = fmaxf(acc.x * dv + base.x, 0.0f);
    float ay = fmaxf(acc.y * dv + base.y, 0.0f);

    float2 y = ((const float2*)g_Y)[n * 32 + lane];
    float2 x = ((const float2*)g_X)[n * 32 + lane];
    float ynx = y.x + ((ax - y.x) - x.x);
    float yny = y.y + ((ay - y.y) - x.y);
    ((float2*)g_Y)[n * 32 + lane] = make_float2(ynx, yny);
    ((float2*)g_X)[n * 32 + lane] = make_float2(x.x + ynx, x.y + yny);
}

// ---------------------------------------------------------------------------
// Decoder + pooling: out[batch[n]] += X[n]@dec_W + dec_b
// ---------------------------------------------------------------------------
__global__ void k_decode_pool(const float* __restrict__ decW, const float* __restrict__ decB,
                              const int* __restrict__ batch, float* __restrict__ out) {
    __shared__ float dw[64];
    int t = threadIdx.x;  // 256 = 8 warps, one node per warp
    if (t < 64) dw[t] = decW[t];
    __syncthreads();
    int lane = t & 31;
    int n = blockIdx.x * 8 + (t >> 5);
    if (n >= NN) return;
    float v = g_X[n * 64 + lane] * dw[lane] + g_X[n * 64 + lane + 32] * dw[lane + 32];
#pragma unroll
    for (int o = 16; o; o >>= 1) v += __shfl_xor_sync(0xffffffffu, v, o);
    if (lane == 0) atomicAdd(&out[batch[n]], v + decB[0]);
}

// ---------------------------------------------------------------------------
extern "C" void kernel_launch(void* const* d_in, const int* in_sizes, int n_in,
                              void* d_out, int out_size) {
    const float* x     = (const float*)d_in[0];
    const float* pos   = (const float*)d_in[1];
    const int*   ei    = (const int*)d_in[2];
    const int*   batch = (const int*)d_in[3];
    const float* encW  = (const float*)d_in[4];
    const float* encB  = (const float*)d_in[5];
    const float* convW = (const float*)d_in[6];
    const float* convB = (const float*)d_in[7];
    const float* resW  = (const float*)d_in[8];
    const float* resB  = (const float*)d_in[9];
    const float* decW  = (const float*)d_in[10];
    const float* decB  = (const float*)d_in[11];
    float* out         = (float*)d_out;

    const int nb_n   = (NN + 255) / 256;
    const int nb_e   = (EE + 255) / 256;
    const int nb_enc = (NN + 3) / 4;
    const int nb_gem = (NN + 63) / 64;
    const int nb_agg = (NN + 7) / 8;

    k_zero<<<nb_n, 256>>>(out);
    k_build<<<nb_e, 256>>>(ei);
    k_encoder<<<nb_enc, 256>>>(x, pos, encW, encB);

    for (int layer = 0; layer < 5; layer++) {
        k_layer_gemm<<<nb_gem, 256>>>(convW, convB, resW, resB);
        k_agg_update<<<nb_agg, 256>>>();
    }

    k_decode_pool<<<nb_agg, 256>>>(decW, decB, batch, out);
}

// round 9
// speedup vs baseline: 1.7537x; 1.7537x over previous
#include <cuda_runtime.h>
#include <cstdint>

// Problem constants
#define NN 50000
#define EE 800000
#define NH 64
#define NGR 500
#define MAXD 96   // adjacency slot stride (Poisson(16); P(deg>96) ~ 0)

// Scratch (device globals; no allocation allowed)
__device__ __align__(16) float g_X[NN * NH];
__device__ __align__(16) float g_Y[NN * NH];
__device__ __align__(16) float g_hWp[NN * NH];   // (X @ conv_W) * dinv[row]
__device__ __align__(16) float g_base[NN * NH];  // X @ res_W + conv_b + res_b
__device__ int g_cnt[NN];
__device__ int g_adj[NN * MAXD];

// XOR swizzle: row-major [r][k], stride 64, k XOR'd by (r&7)*4 -> conflict-free
// for the tf32 mma fragment access pattern (lane = 4*g + tg; k=tg(+4), r/n=g).
#define SWZ(r, k) (((r) << 6) | ((k) ^ (((r) & 7) << 2)))

static __device__ __forceinline__ uint32_t f2tf32(float v) {
    uint32_t r;
    asm("cvt.rna.tf32.f32 %0, %1;" : "=r"(r) : "f"(v));
    return r;
}

static __device__ __forceinline__ void mma_tf32(float c[4], const uint32_t a[4],
                                                uint32_t b0, uint32_t b1) {
    asm volatile(
        "mma.sync.aligned.m16n8k8.row.col.f32.tf32.tf32.f32 "
        "{%0,%1,%2,%3}, {%4,%5,%6,%7}, {%8,%9}, {%0,%1,%2,%3};"
        : "+f"(c[0]), "+f"(c[1]), "+f"(c[2]), "+f"(c[3])
        : "r"(a[0]), "r"(a[1]), "r"(a[2]), "r"(a[3]), "r"(b0), "r"(b1));
}

// ---------------------------------------------------------------------------
// Zero counters + output
// ---------------------------------------------------------------------------
__global__ void k_zero(float* __restrict__ out) {
    int i = blockIdx.x * 256 + threadIdx.x;
    if (i < NN) g_cnt[i] = 0;
    if (i < NGR) out[i] = 0.0f;
}

// ---------------------------------------------------------------------------
// Build fixed-stride adjacency (incoming edges per dst) + in-degree counts
// ---------------------------------------------------------------------------
__global__ void k_build(const int* __restrict__ ei) {
    int e = blockIdx.x * 256 + threadIdx.x;
    if (e >= EE) return;
    int s = ei[e];
    int d = ei[EE + e];
    int pos = atomicAdd(&g_cnt[d], 1);
    if (pos < MAXD) g_adj[d * MAXD + pos] = s;
}

// ---------------------------------------------------------------------------
// Encoder: Y = X = concat(x, pos) @ enc_W + enc_b
// ---------------------------------------------------------------------------
__global__ void k_encoder(const float* __restrict__ x, const float* __restrict__ pos,
                          const float* __restrict__ encW, const float* __restrict__ encB) {
    __shared__ float Ws[16 * 64];
    int t = threadIdx.x;  // 256
    for (int i = t; i < 16 * 64; i += 256) Ws[i] = encW[i];
    __syncthreads();
    int c = t & 63;
    int n = blockIdx.x * 4 + (t >> 6);
    if (n >= NN) return;
    float acc = 0.0f;
#pragma unroll
    for (int f = 0; f < 14; f++) acc += x[n * 14 + f] * Ws[f * 64 + c];
    acc += pos[n * 2 + 0] * Ws[14 * 64 + c];
    acc += pos[n * 2 + 1] * Ws[15 * 64 + c];
    acc += encB[c];
    g_Y[n * 64 + c] = acc;
    g_X[n * 64 + c] = acc;
}

// ---------------------------------------------------------------------------
// TF32 tensor-core dual GEMM. Block: 64 rows x 128 cols (cols 0-63: conv,
// 64-127: res). 256 threads = 8 warps (4 M-groups x 2 N-groups); each warp
// one m16 tile x 8 n8 tiles, K=64 in 8 k8 steps.
//   g_hWp  = (X @ conv_W) * dinv[row]
//   g_base =  X @ res_W + conv_b + res_b
// ---------------------------------------------------------------------------
__global__ void k_layer_gemm(const float* __restrict__ convW, const float* __restrict__ convB,
                             const float* __restrict__ resW, const float* __restrict__ resB) {
    __shared__ uint32_t Xs[64 * 64];    // [row][k], swizzled, tf32 bits (16 KB)
    __shared__ uint32_t Wt[128 * 64];   // [n][k],  swizzled, tf32 bits (32 KB)
    int t = threadIdx.x;  // 256
    int row0 = blockIdx.x * 64;

    // W combined + transposed into [n][k]; convW/resW are [k][n] row-major.
    for (int i = t; i < 4096; i += 256) {
        int k = i >> 6, n = i & 63;
        Wt[SWZ(n, k)] = f2tf32(convW[i]);
        Wt[SWZ(n + 64, k)] = f2tf32(resW[i]);
    }
    // X tile (clamped; stores guarded)
    for (int i = t; i < 4096; i += 256) {
        int r = i >> 6, k = i & 63;
        int node = row0 + r;
        if (node >= NN) node = NN - 1;
        Xs[SWZ(r, k)] = f2tf32(g_X[node * 64 + k]);
    }
    __syncthreads();

    int lane = t & 31, w = t >> 5;
    int wm = w & 3, wn = w >> 2;         // 4 M-groups (16 rows), 2 N-groups (64 cols)
    int g = lane >> 2, tg = lane & 3;    // groupID, threadID_in_group

    float acc[8][4];
#pragma unroll
    for (int nt = 0; nt < 8; nt++)
#pragma unroll
        for (int j = 0; j < 4; j++) acc[nt][j] = 0.0f;

    int rA = wm * 16 + g;
#pragma unroll
    for (int ks = 0; ks < 8; ks++) {
        int k0 = ks * 8;
        uint32_t a[4];
        a[0] = Xs[SWZ(rA, k0 + tg)];
        a[1] = Xs[SWZ(rA + 8, k0 + tg)];
        a[2] = Xs[SWZ(rA, k0 + tg + 4)];
        a[3] = Xs[SWZ(rA + 8, k0 + tg + 4)];
#pragma unroll
        for (int nt = 0; nt < 8; nt++) {
            int n = wn * 64 + nt * 8 + g;
            uint32_t b0 = Wt[SWZ(n, k0 + tg)];
            uint32_t b1 = Wt[SWZ(n, k0 + tg + 4)];
            mma_tf32(acc[nt], a, b0, b1);
        }
    }

    // Epilogue. c0,c1: row g, cols 2*tg,2*tg+1 ; c2,c3: row g+8, same cols.
    if (wn == 0) {
        // conv path -> g_hWp, scaled by dinv
#pragma unroll
        for (int half = 0; half < 2; half++) {
            int node = row0 + rA + half * 8;
            if (node < NN) {
                float dv = rsqrtf((float)g_cnt[node] + 1.0f);
#pragma unroll
                for (int nt = 0; nt < 8; nt++) {
                    int col = nt * 8 + 2 * tg;
                    float2 v = make_float2(acc[nt][2 * half] * dv, acc[nt][2 * half + 1] * dv);
                    *(float2*)&g_hWp[node * 64 + col] = v;
                }
            }
        }
    } else {
        // res path -> g_base, plus biases
#pragma unroll
        for (int half = 0; half < 2; half++) {
            int node = row0 + rA + half * 8;
            if (node < NN) {
#pragma unroll
                for (int nt = 0; nt < 8; nt++) {
                    int col = nt * 8 + 2 * tg;
                    float b0v = convB[col] + resB[col];
                    float b1v = convB[col + 1] + resB[col + 1];
                    float2 v = make_float2(acc[nt][2 * half] + b0v, acc[nt][2 * half + 1] + b1v);
                    *(float2*)&g_base[node * 64 + col] = v;
                }
            }
        }
    }
}

// ---------------------------------------------------------------------------
// Gather-aggregate + fused GraphCON update. One warp per node, float2/lane.
//   agg = dinv[n] * (sum_{incoming} hW'[src] + hW'[n]) + base[n]
// ---------------------------------------------------------------------------
__global__ void k_agg_update() {
    int t = threadIdx.x;  // 256 = 8 warps
    int lane = t & 31;
    int n = blockIdx.x * 8 + (t >> 5);
    if (n >= NN) return;

    int deg = g_cnt[n];
    if (deg > MAXD) deg = MAXD;
    const float2* __restrict__ hw2 = (const float2*)g_hWp;

    float2 acc = hw2[n * 32 + lane];  // self-loop term
    const int* __restrict__ row = &g_adj[n * MAXD];
    for (int b = 0; b < deg; b += 32) {
        int id = (b + lane < deg) ? row[b + lane] : 0;
        int cnt = deg - b; if (cnt > 32) cnt = 32;
        for (int i = 0; i < cnt; i++) {
            int s = __shfl_sync(0xffffffffu, id, i);
            float2 v = hw2[s * 32 + lane];
            acc.x += v.x; acc.y += v.y;
        }
    }

    float dv = rsqrtf((float)g_cnt[n] + 1.0f);
    float2 base = ((const float2*)g_base)[n * 32 + lane];
    float ax = fmaxf(acc.x * dv + base.x, 0.0f);
    float ay = fmaxf(acc.y * dv + base.y, 0.0f);

    float2 y = ((const float2*)g_Y)[n * 32 + lane];
    float2 x = ((const float2*)g_X)[n * 32 + lane];
    float ynx = y.x + ((ax - y.x) - x.x);
    float yny = y.y + ((ay - y.y) - x.y);
    ((float2*)g_Y)[n * 32 + lane] = make_float2(ynx, yny);
    ((float2*)g_X)[n * 32 + lane] = make_float2(x.x + ynx, x.y + yny);
}

// ---------------------------------------------------------------------------
// Decoder + pooling: out[batch[n]] += X[n]@dec_W + dec_b
// ---------------------------------------------------------------------------
__global__ void k_decode_pool(const float* __restrict__ decW, const float* __restrict__ decB,
                              const int* __restrict__ batch, float* __restrict__ out) {
    __shared__ float dw[64];
    int t = threadIdx.x;  // 256 = 8 warps, one node per warp
    if (t < 64) dw[t] = decW[t];
    __syncthreads();
    int lane = t & 31;
    int n = blockIdx.x * 8 + (t >> 5);
    if (n >= NN) return;
    float v = g_X[n * 64 + lane] * dw[lane] + g_X[n * 64 + lane + 32] * dw[lane + 32];
#pragma unroll
    for (int o = 16; o; o >>= 1) v += __shfl_xor_sync(0xffffffffu, v, o);
    if (lane == 0) atomicAdd(&out[batch[n]], v + decB[0]);
}

// ---------------------------------------------------------------------------
extern "C" void kernel_launch(void* const* d_in, const int* in_sizes, int n_in,
                              void* d_out, int out_size) {
    const float* x     = (const float*)d_in[0];
    const float* pos   = (const float*)d_in[1];
    const int*   ei    = (const int*)d_in[2];
    const int*   batch = (const int*)d_in[3];
    const float* encW  = (const float*)d_in[4];
    const float* encB  = (const float*)d_in[5];
    const float* convW = (const float*)d_in[6];
    const float* convB = (const float*)d_in[7];
    const float* resW  = (const float*)d_in[8];
    const float* resB  = (const float*)d_in[9];
    const float* decW  = (const float*)d_in[10];
    const float* decB  = (const float*)d_in[11];
    float* out         = (float*)d_out;

    const int nb_n   = (NN + 255) / 256;
    const int nb_e   = (EE + 255) / 256;
    const int nb_enc = (NN + 3) / 4;
    const int nb_gem = (NN + 63) / 64;
    const int nb_agg = (NN + 7) / 8;

    k_zero<<<nb_n, 256>>>(out);
    k_build<<<nb_e, 256>>>(ei);
    k_encoder<<<nb_enc, 256>>>(x, pos, encW, encB);

    for (int layer = 0; layer < 5; layer++) {
        k_layer_gemm<<<nb_gem, 256>>>(convW, convB, resW, resB);
        k_agg_update<<<nb_agg, 256>>>();
    }

    k_decode_pool<<<nb_agg, 256>>>(decW, decB, batch, out);
}

// round 12
// speedup vs baseline: 2.1506x; 1.2263x over previous
#include <cuda_runtime.h>
#include <cstdint>

// Problem constants
#define NN 50000
#define EE 800000
#define NH 64
#define NGR 500
#define MAXD 96   // adjacency slot stride (Poisson(16); P(deg>96) ~ 0)

// Scratch (device globals; no allocation allowed)
__device__ __align__(16) float g_X[NN * NH];
__device__ __align__(16) float g_Y[NN * NH];
__device__ __align__(16) float g_hWp[NN * NH];   // (X @ conv_W) * dinv[row]
__device__ __align__(16) float g_base[NN * NH];  // X @ res_W + conv_b + res_b
__device__ int g_cnt[NN];
__device__ int g_adj[NN * MAXD];
__device__ __align__(16) uint32_t g_Wt[128 * 64]; // swizzled tf32 [n][k] (conv|res)
__device__ float g_bias[64];                      // convB + resB

// XOR swizzle: row-major [r][k], stride 64, k XOR'd by (r&7)*4 -> conflict-free
// for the tf32 mma fragment access pattern (lane = 4*g + tg; k=tg(+4), r/n=g).
#define SWZ(r, k) (((r) << 6) | ((k) ^ (((r) & 7) << 2)))

static __device__ __forceinline__ uint32_t f2tf32(float v) {
    uint32_t r;
    asm("cvt.rna.tf32.f32 %0, %1;" : "=r"(r) : "f"(v));
    return r;
}

static __device__ __forceinline__ void mma_tf32(float c[4], const uint32_t a[4],
                                                uint32_t b0, uint32_t b1) {
    asm volatile(
        "mma.sync.aligned.m16n8k8.row.col.f32.tf32.tf32.f32 "
        "{%0,%1,%2,%3}, {%4,%5,%6,%7}, {%8,%9}, {%0,%1,%2,%3};"
        : "+f"(c[0]), "+f"(c[1]), "+f"(c[2]), "+f"(c[3])
        : "r"(a[0]), "r"(a[1]), "r"(a[2]), "r"(a[3]), "r"(b0), "r"(b1));
}

// ---------------------------------------------------------------------------
// Zero counters + output
// ---------------------------------------------------------------------------
__global__ void k_zero(float* __restrict__ out) {
    int i = blockIdx.x * 256 + threadIdx.x;
    if (i < NN) g_cnt[i] = 0;
    if (i < NGR) out[i] = 0.0f;
}

// ---------------------------------------------------------------------------
// One-time weight prep: tf32-convert + swizzle into g_Wt; combined bias.
// ---------------------------------------------------------------------------
__global__ void k_wprep(const float* __restrict__ convW, const float* __restrict__ resW,
                        const float* __restrict__ convB, const float* __restrict__ resB) {
    int t = blockIdx.x * 256 + threadIdx.x;   // 32 blocks x 256 = 8192
    if (t < 64) g_bias[t] = convB[t] + resB[t];
    if (t >= 8192) return;
    int n = t >> 6, k = t & 63;               // n in [0,128), k in [0,64)
    float v = (n < 64) ? convW[k * 64 + n] : resW[k * 64 + (n - 64)];
    g_Wt[SWZ(n, k)] = f2tf32(v);
}

// ---------------------------------------------------------------------------
// Build fixed-stride adjacency (incoming edges per dst) + in-degree counts
// ---------------------------------------------------------------------------
__global__ void k_build(const int* __restrict__ ei) {
    int e = blockIdx.x * 256 + threadIdx.x;
    if (e >= EE) return;
    int s = ei[e];
    int d = ei[EE + e];
    int pos = atomicAdd(&g_cnt[d], 1);
    if (pos < MAXD) g_adj[d * MAXD + pos] = s;
}

// ---------------------------------------------------------------------------
// Encoder: Y = X = concat(x, pos) @ enc_W + enc_b
// ---------------------------------------------------------------------------
__global__ void k_encoder(const float* __restrict__ x, const float* __restrict__ pos,
                          const float* __restrict__ encW, const float* __restrict__ encB) {
    __shared__ float Ws[16 * 64];
    int t = threadIdx.x;  // 256
    for (int i = t; i < 16 * 64; i += 256) Ws[i] = encW[i];
    __syncthreads();
    int c = t & 63;
    int n = blockIdx.x * 4 + (t >> 6);
    if (n >= NN) return;
    float acc = 0.0f;
#pragma unroll
    for (int f = 0; f < 14; f++) acc += x[n * 14 + f] * Ws[f * 64 + c];
    acc += pos[n * 2 + 0] * Ws[14 * 64 + c];
    acc += pos[n * 2 + 1] * Ws[15 * 64 + c];
    acc += encB[c];
    g_Y[n * 64 + c] = acc;
    g_X[n * 64 + c] = acc;
}

// ---------------------------------------------------------------------------
// TF32 tensor-core dual GEMM. Block: 64 rows x 128 cols (cols 0-63: conv,
// 64-127: res). 256 threads = 8 warps (4 M x 2 N); warp: m16 x 8*n8, K=64.
// Fills are conflict-free: W = linear uint4 copy of pre-swizzled g_Wt;
// X = linear smem index with inverse-swizzled (still coalesced) gmem read.
// ---------------------------------------------------------------------------
__global__ void k_layer_gemm() {
    __shared__ uint32_t Xs[64 * 64];    // 16 KB
    __shared__ uint32_t Wt[128 * 64];   // 32 KB
    int t = threadIdx.x;  // 256
    int row0 = blockIdx.x * 64;

    // Linear copy of pre-swizzled W (coalesced, conflict-free)
    {
        const uint4* __restrict__ src = (const uint4*)g_Wt;
        uint4* dst = (uint4*)Wt;
#pragma unroll
        for (int i = 0; i < 8; i++) dst[t + i * 256] = src[t + i * 256];
    }
    // X tile: linear smem store, inverse-swizzle on the (coalesced) gmem read
#pragma unroll
    for (int i = 0; i < 16; i++) {
        int idx = t + i * 256;          // = SWZ(r, k') destination
        int r = idx >> 6, kp = idx & 63;
        int k = kp ^ ((r & 7) << 2);    // inverse swizzle (XOR involution)
        int node = row0 + r;
        if (node >= NN) node = NN - 1;  // clamp; stores guarded
        Xs[idx] = f2tf32(g_X[node * 64 + k]);
    }
    __syncthreads();

    int lane = t & 31, w = t >> 5;
    int wm = w & 3, wn = w >> 2;         // 4 M-groups (16 rows), 2 N-groups
    int g = lane >> 2, tg = lane & 3;    // groupID, threadID_in_group

    float acc[8][4];
#pragma unroll
    for (int nt = 0; nt < 8; nt++)
#pragma unroll
        for (int j = 0; j < 4; j++) acc[nt][j] = 0.0f;

    int rA = wm * 16 + g;
#pragma unroll
    for (int ks = 0; ks < 8; ks++) {
        int k0 = ks * 8;
        uint32_t a[4];
        a[0] = Xs[SWZ(rA, k0 + tg)];
        a[1] = Xs[SWZ(rA + 8, k0 + tg)];
        a[2] = Xs[SWZ(rA, k0 + tg + 4)];
        a[3] = Xs[SWZ(rA + 8, k0 + tg + 4)];
#pragma unroll
        for (int nt = 0; nt < 8; nt++) {
            int n = wn * 64 + nt * 8 + g;
            uint32_t b0 = Wt[SWZ(n, k0 + tg)];
            uint32_t b1 = Wt[SWZ(n, k0 + tg + 4)];
            mma_tf32(acc[nt], a, b0, b1);
        }
    }

    // Epilogue. c0,c1: row g, cols 2*tg,2*tg+1 ; c2,c3: row g+8.
    if (wn == 0) {
#pragma unroll
        for (int half = 0; half < 2; half++) {
            int node = row0 + rA + half * 8;
            if (node < NN) {
                float dv = rsqrtf((float)g_cnt[node] + 1.0f);
#pragma unroll
                for (int nt = 0; nt < 8; nt++) {
                    int col = nt * 8 + 2 * tg;
                    float2 v = make_float2(acc[nt][2 * half] * dv, acc[nt][2 * half + 1] * dv);
                    *(float2*)&g_hWp[node * 64 + col] = v;
                }
            }
        }
    } else {
#pragma unroll
        for (int half = 0; half < 2; half++) {
            int node = row0 + rA + half * 8;
            if (node < NN) {
#pragma unroll
                for (int nt = 0; nt < 8; nt++) {
                    int col = nt * 8 + 2 * tg;
                    float2 v = make_float2(acc[nt][2 * half] + g_bias[col],
                                           acc[nt][2 * half + 1] + g_bias[col + 1]);
                    *(float2*)&g_base[node * 64 + col] = v;
                }
            }
        }
    }
}

// ---------------------------------------------------------------------------
// Gather-aggregate + fused GraphCON update. One warp per node, float2/lane.
//   agg = dinv[n] * (sum_{incoming} hW'[src] + hW'[n]) + base[n]
// ---------------------------------------------------------------------------
__global__ void k_agg_update() {
    int t = threadIdx.x;  // 256 = 8 warps
    int lane = t & 31;
    int n = blockIdx.x * 8 + (t >> 5);
    if (n >= NN) return;

    int deg = g_cnt[n];
    if (deg > MAXD) deg = MAXD;
    const float2* __restrict__ hw2 = (const float2*)g_hWp;

    float2 acc = hw2[n * 32 + lane];  // self-loop term
    const int* __restrict__ row = &g_adj[n * MAXD];
    for (int b = 0; b < deg; b += 32) {
        int id = (b + lane < deg) ? row[b + lane] : 0;
        int cnt = deg - b; if (cnt > 32) cnt = 32;
        for (int i = 0; i < cnt; i++) {
            int s = __shfl_sync(0xffffffffu, id, i);
            float2 v = hw2[s * 32 + lane];
            acc.x += v.x; acc.y += v.y;
        }
    }

    float dv = rsqrtf((float)g_cnt[n] + 1.0f);
    float2 base = ((const float2*)g_base)[n * 32 + lane];
    float ax = fmaxf(acc.x * dv + base.x, 0.0f);
    float ay = fmaxf(acc.y * dv + base.y, 0.0f);

    float2 y = ((const float2*)g_Y)[n * 32 + lane];
    float2 x = ((const float2*)g_X)[n * 32 + lane];
    float ynx = y.x + ((ax - y.x) - x.x);
    float yny = y.y + ((ay - y.y) - x.y);
    ((float2*)g_Y)[n * 32 + lane] = make_float2(ynx, yny);
    ((float2*)g_X)[n * 32 + lane] = make_float2(x.x + ynx, x.y + yny);
}

// ---------------------------------------------------------------------------
// Decoder + pooling: out[batch[n]] += X[n]@dec_W + dec_b
// ---------------------------------------------------------------------------
__global__ void k_decode_pool(const float* __restrict__ decW, const float* __restrict__ decB,
                              const int* __restrict__ batch, float* __restrict__ out) {
    __shared__ float dw[64];
    int t = threadIdx.x;  // 256 = 8 warps, one node per warp
    if (t < 64) dw[t] = decW[t];
    __syncthreads();
    int lane = t & 31;
    int n = blockIdx.x * 8 + (t >> 5);
    if (n >= NN) return;
    float v = g_X[n * 64 + lane] * dw[lane] + g_X[n * 64 + lane + 32] * dw[lane + 32];
#pragma unroll
    for (int o = 16; o; o >>= 1) v += __shfl_xor_sync(0xffffffffu, v, o);
    if (lane == 0) atomicAdd(&out[batch[n]], v + decB[0]);
}

// ---------------------------------------------------------------------------
extern "C" void kernel_launch(void* const* d_in, const int* in_sizes, int n_in,
                              void* d_out, int out_size) {
    const float* x     = (const float*)d_in[0];
    const float* pos   = (const float*)d_in[1];
    const int*   ei    = (const int*)d_in[2];
    const int*   batch = (const int*)d_in[3];
    const float* encW  = (const float*)d_in[4];
    const float* encB  = (const float*)d_in[5];
    const float* convW = (const float*)d_in[6];
    const float* convB = (const float*)d_in[7];
    const float* resW  = (const float*)d_in[8];
    const float* resB  = (const float*)d_in[9];
    const float* decW  = (const float*)d_in[10];
    const float* decB  = (const float*)d_in[11];
    float* out         = (float*)d_out;

    const int nb_n   = (NN + 255) / 256;
    const int nb_e   = (EE + 255) / 256;
    const int nb_enc = (NN + 3) / 4;
    const int nb_gem = (NN + 63) / 64;
    const int nb_agg = (NN + 7) / 8;

    k_zero<<<nb_n, 256>>>(out);
    k_wprep<<<32, 256>>>(convW, resW, convB, resB);
    k_build<<<nb_e, 256>>>(ei);
    k_encoder<<<nb_enc, 256>>>(x, pos, encW, encB);

    for (int layer = 0; layer < 5; layer++) {
        k_layer_gemm<<<nb_gem, 256>>>();
        k_agg_update<<<nb_agg, 256>>>();
    }

    k_decode_pool<<<nb_agg, 256>>>(decW, decB, batch, out);
}

// round 13
// speedup vs baseline: 2.4146x; 1.1227x over previous
#include <cuda_runtime.h>
#include <cuda_fp16.h>
#include <cstdint>

// Problem constants
#define NN 50000
#define EE 800000
#define NH 64
#define NGR 500
#define MAXD 96   // adjacency slot stride (Poisson(16); P(deg>96) ~ 0)

// Scratch (device globals; no allocation allowed)
__device__ __align__(16) float   g_X[NN * NH];
__device__ __align__(16) __half2 g_hWph[NN * 32];  // (X @ conv_W) * dinv[row], fp16 pairs
__device__ __align__(16) float   g_base[NN * NH];  // X @ res_W + conv_b + res_b
__device__ int g_cnt[NN];
__device__ int g_adj[NN * MAXD];
__device__ __align__(16) uint32_t g_Wt[128 * 64];  // swizzled tf32 [n][k] (conv|res)
__device__ float g_bias[64];                       // convB + resB

// XOR swizzle: row-major [r][k], stride 64, k XOR'd by (r&7)*4 -> conflict-free
// for the tf32 mma fragment access pattern (lane = 4*g + tg; k=tg(+4), r/n=g).
#define SWZ(r, k) (((r) << 6) | ((k) ^ (((r) & 7) << 2)))

static __device__ __forceinline__ uint32_t f2tf32(float v) {
    uint32_t r;
    asm("cvt.rna.tf32.f32 %0, %1;" : "=r"(r) : "f"(v));
    return r;
}

static __device__ __forceinline__ void mma_tf32(float c[4], const uint32_t a[4],
                                                uint32_t b0, uint32_t b1) {
    asm volatile(
        "mma.sync.aligned.m16n8k8.row.col.f32.tf32.tf32.f32 "
        "{%0,%1,%2,%3}, {%4,%5,%6,%7}, {%8,%9}, {%0,%1,%2,%3};"
        : "+f"(c[0]), "+f"(c[1]), "+f"(c[2]), "+f"(c[3])
        : "r"(a[0]), "r"(a[1]), "r"(a[2]), "r"(a[3]), "r"(b0), "r"(b1));
}

// ---------------------------------------------------------------------------
// Zero counters + output
// ---------------------------------------------------------------------------
__global__ void k_zero(float* __restrict__ out) {
    int i = blockIdx.x * 256 + threadIdx.x;
    if (i < NN) g_cnt[i] = 0;
    if (i < NGR) out[i] = 0.0f;
}

// ---------------------------------------------------------------------------
// One-time weight prep: tf32-convert + swizzle into g_Wt; combined bias.
// ---------------------------------------------------------------------------
__global__ void k_wprep(const float* __restrict__ convW, const float* __restrict__ resW,
                        const float* __restrict__ convB, const float* __restrict__ resB) {
    int t = blockIdx.x * 256 + threadIdx.x;   // 32 blocks x 256 = 8192
    if (t < 64) g_bias[t] = convB[t] + resB[t];
    if (t >= 8192) return;
    int n = t >> 6, k = t & 63;               // n in [0,128), k in [0,64)
    float v = (n < 64) ? convW[k * 64 + n] : resW[k * 64 + (n - 64)];
    g_Wt[SWZ(n, k)] = f2tf32(v);
}

// ---------------------------------------------------------------------------
// Build fixed-stride adjacency (incoming edges per dst) + in-degree counts
// ---------------------------------------------------------------------------
__global__ void k_build(const int* __restrict__ ei) {
    int e = blockIdx.x * 256 + threadIdx.x;
    if (e >= EE) return;
    int s = ei[e];
    int d = ei[EE + e];
    int pos = atomicAdd(&g_cnt[d], 1);
    if (pos < MAXD) g_adj[d * MAXD + pos] = s;
}

// ---------------------------------------------------------------------------
// Encoder: X = concat(x, pos) @ enc_W + enc_b  (Y eliminated algebraically).
// 64 nodes/block, smem-staged inputs, coalesced loads + stores.
// ---------------------------------------------------------------------------
__global__ void k_encoder(const float* __restrict__ x, const float* __restrict__ pos,
                          const float* __restrict__ encW, const float* __restrict__ encB) {
    __shared__ float inp[64][17];   // 16 feats, pad to 17
    __shared__ float Ws[16][64];
    __shared__ float bs[64];
    int t = threadIdx.x;  // 256
    int n0 = blockIdx.x * 64;

    for (int i = t; i < 1024; i += 256) Ws[i >> 6][i & 63] = encW[i];
    if (t < 64) bs[t] = encB[t];
    for (int i = t; i < 64 * 14; i += 256) {
        int r = i / 14, f = i - r * 14;
        int node = n0 + r; if (node >= NN) node = NN - 1;
        inp[r][f] = x[node * 14 + f];
    }
    if (t < 128) {
        int r = t >> 1, f = t & 1;
        int node = n0 + r; if (node >= NN) node = NN - 1;
        inp[r][14 + f] = pos[node * 2 + f];
    }
    __syncthreads();

    int c = t & 63;
    int rq = t >> 6;  // 0..3
#pragma unroll 4
    for (int j = 0; j < 16; j++) {
        int r = rq * 16 + j;
        int node = n0 + r;
        if (node >= NN) break;
        float acc = bs[c];
#pragma unroll
        for (int f = 0; f < 16; f++) acc += inp[r][f] * Ws[f][c];
        g_X[node * 64 + c] = acc;
    }
}

// ---------------------------------------------------------------------------
// TF32 tensor-core dual GEMM. Block: 64 rows x 128 cols (cols 0-63: conv,
// 64-127: res). 256 threads = 8 warps (4 M x 2 N); warp: m16 x 8*n8, K=64.
//   g_hWph = half2( (X @ conv_W) * dinv[row] )
//   g_base =  X @ res_W + conv_b + res_b
// ---------------------------------------------------------------------------
__global__ void k_layer_gemm() {
    __shared__ uint32_t Xs[64 * 64];    // 16 KB
    __shared__ uint32_t Wt[128 * 64];   // 32 KB
    int t = threadIdx.x;  // 256
    int row0 = blockIdx.x * 64;

    // Linear copy of pre-swizzled W (coalesced, conflict-free)
    {
        const uint4* __restrict__ src = (const uint4*)g_Wt;
        uint4* dst = (uint4*)Wt;
#pragma unroll
        for (int i = 0; i < 8; i++) dst[t + i * 256] = src[t + i * 256];
    }
    // X tile: linear smem store, inverse-swizzle on the (coalesced) gmem read
#pragma unroll
    for (int i = 0; i < 16; i++) {
        int idx = t + i * 256;          // = SWZ(r, k') destination
        int r = idx >> 6, kp = idx & 63;
        int k = kp ^ ((r & 7) << 2);    // inverse swizzle (XOR involution)
        int node = row0 + r;
        if (node >= NN) node = NN - 1;  // clamp; stores guarded
        Xs[idx] = f2tf32(g_X[node * 64 + k]);
    }
    __syncthreads();

    int lane = t & 31, w = t >> 5;
    int wm = w & 3, wn = w >> 2;         // 4 M-groups (16 rows), 2 N-groups
    int g = lane >> 2, tg = lane & 3;    // groupID, threadID_in_group

    float acc[8][4];
#pragma unroll
    for (int nt = 0; nt < 8; nt++)
#pragma unroll
        for (int j = 0; j < 4; j++) acc[nt][j] = 0.0f;

    int rA = wm * 16 + g;
#pragma unroll
    for (int ks = 0; ks < 8; ks++) {
        int k0 = ks * 8;
        uint32_t a[4];
        a[0] = Xs[SWZ(rA, k0 + tg)];
        a[1] = Xs[SWZ(rA + 8, k0 + tg)];
        a[2] = Xs[SWZ(rA, k0 + tg + 4)];
        a[3] = Xs[SWZ(rA + 8, k0 + tg + 4)];
#pragma unroll
        for (int nt = 0; nt < 8; nt++) {
            int n = wn * 64 + nt * 8 + g;
            uint32_t b0 = Wt[SWZ(n, k0 + tg)];
            uint32_t b1 = Wt[SWZ(n, k0 + tg + 4)];
            mma_tf32(acc[nt], a, b0, b1);
        }
    }

    // Epilogue. c0,c1: row g, cols 2*tg,2*tg+1 ; c2,c3: row g+8.
    if (wn == 0) {
#pragma unroll
        for (int half = 0; half < 2; half++) {
            int node = row0 + rA + half * 8;
            if (node < NN) {
                float dv = rsqrtf((float)g_cnt[node] + 1.0f);
#pragma unroll
                for (int nt = 0; nt < 8; nt++) {
                    int cp = nt * 4 + tg;   // col-pair index
                    g_hWph[node * 32 + cp] =
                        __floats2half2_rn(acc[nt][2 * half] * dv, acc[nt][2 * half + 1] * dv);
                }
            }
        }
    } else {
#pragma unroll
        for (int half = 0; half < 2; half++) {
            int node = row0 + rA + half * 8;
            if (node < NN) {
#pragma unroll
                for (int nt = 0; nt < 8; nt++) {
                    int col = nt * 8 + 2 * tg;
                    float2 v = make_float2(acc[nt][2 * half] + g_bias[col],
                                           acc[nt][2 * half + 1] + g_bias[col + 1]);
                    *(float2*)&g_base[node * 64 + col] = v;
                }
            }
        }
    }
}

// ---------------------------------------------------------------------------
// Gather-aggregate + fused update. One warp per node, half2 gather, fp32 acc.
//   X = relu( dinv[n] * (sum_{in} hW'[src] + hW'[n]) + base[n] )
// ---------------------------------------------------------------------------
__global__ void k_agg_update() {
    int t = threadIdx.x;  // 256 = 8 warps
    int lane = t & 31;
    int n = blockIdx.x * 8 + (t >> 5);
    if (n >= NN) return;

    int deg = g_cnt[n];
    if (deg > MAXD) deg = MAXD;

    float2 acc = __half22float2(g_hWph[n * 32 + lane]);  // self-loop term
    const int* __restrict__ row = &g_adj[n * MAXD];
    for (int b = 0; b < deg; b += 32) {
        int id = (b + lane < deg) ? row[b + lane] : 0;
        int cnt = deg - b; if (cnt > 32) cnt = 32;
        for (int i = 0; i < cnt; i++) {
            int s = __shfl_sync(0xffffffffu, id, i);
            float2 v = __half22float2(g_hWph[s * 32 + lane]);
            acc.x += v.x; acc.y += v.y;
        }
    }

    float dv = rsqrtf((float)g_cnt[n] + 1.0f);
    float2 base = ((const float2*)g_base)[n * 32 + lane];
    float ax = fmaxf(fmaf(acc.x, dv, base.x), 0.0f);
    float ay = fmaxf(fmaf(acc.y, dv, base.y), 0.0f);
    ((float2*)g_X)[n * 32 + lane] = make_float2(ax, ay);
}

// ---------------------------------------------------------------------------
// Decoder + pooling: out[batch[n]] += X[n]@dec_W + dec_b
// ---------------------------------------------------------------------------
__global__ void k_decode_pool(const float* __restrict__ decW, const float* __restrict__ decB,
                              const int* __restrict__ batch, float* __restrict__ out) {
    __shared__ float dw[64];
    int t = threadIdx.x;  // 256 = 8 warps, one node per warp
    if (t < 64) dw[t] = decW[t];
    __syncthreads();
    int lane = t & 31;
    int n = blockIdx.x * 8 + (t >> 5);
    if (n >= NN) return;
    float v = g_X[n * 64 + lane] * dw[lane] + g_X[n * 64 + lane + 32] * dw[lane + 32];
#pragma unroll
    for (int o = 16; o; o >>= 1) v += __shfl_xor_sync(0xffffffffu, v, o);
    if (lane == 0) atomicAdd(&out[batch[n]], v + decB[0]);
}

// ---------------------------------------------------------------------------
extern "C" void kernel_launch(void* const* d_in, const int* in_sizes, int n_in,
                              void* d_out, int out_size) {
    const float* x     = (const float*)d_in[0];
    const float* pos   = (const float*)d_in[1];
    const int*   ei    = (const int*)d_in[2];
    const int*   batch = (const int*)d_in[3];
    const float* encW  = (const float*)d_in[4];
    const float* encB  = (const float*)d_in[5];
    const float* convW = (const float*)d_in[6];
    const float* convB = (const float*)d_in[7];
    const float* resW  = (const float*)d_in[8];
    const float* resB  = (const float*)d_in[9];
    const float* decW  = (const float*)d_in[10];
    const float* decB  = (const float*)d_in[11];
    float* out         = (float*)d_out;

    const int nb_n   = (NN + 255) / 256;
    const int nb_e   = (EE + 255) / 256;
    const int nb_64  = (NN + 63) / 64;
    const int nb_agg = (NN + 7) / 8;

    k_zero<<<nb_n, 256>>>(out);
    k_wprep<<<32, 256>>>(convW, resW, convB, resB);
    k_build<<<nb_e, 256>>>(ei);
    k_encoder<<<nb_64, 256>>>(x, pos, encW, encB);

    for (int layer = 0; layer < 5; layer++) {
        k_layer_gemm<<<nb_64, 256>>>();
        k_agg_update<<<nb_agg, 256>>>();
    }

    k_decode_pool<<<nb_agg, 256>>>(decW, decB, batch, out);
}

// round 14
// speedup vs baseline: 2.4258x; 1.0047x over previous
#include <cuda_runtime.h>
#include <cuda_fp16.h>
#include <cstdint>

// Problem constants
#define NN 50000
#define EE 800000
#define NH 64
#define NGR 500
#define MAXD 96   // adjacency slot stride (Poisson(16); P(deg>96) ~ 0)

// Scratch (device globals; no allocation allowed)
__device__ __align__(16) float   g_X[NN * NH];
__device__ __align__(16) __half2 g_hWph[NN * 32];  // (X @ conv_W) * dinv[row], fp16 pairs
__device__ __align__(16) float   g_base[NN * NH];  // X @ res_W + conv_b + res_b
__device__ int g_cnt[NN];
__device__ int g_adj[NN * MAXD];
__device__ __align__(16) uint32_t g_Wt[128 * 64];  // swizzled tf32 [n][k] (conv|res)
__device__ float g_bias[64];                       // convB + resB

// XOR swizzle: row-major [r][k], stride 64, k XOR'd by (r&7)*4 -> conflict-free
// for the tf32 mma fragment access pattern (lane = 4*g + tg; k=tg(+4), r/n=g).
#define SWZ(r, k) (((r) << 6) | ((k) ^ (((r) & 7) << 2)))

static __device__ __forceinline__ uint32_t f2tf32(float v) {
    uint32_t r;
    asm("cvt.rna.tf32.f32 %0, %1;" : "=r"(r) : "f"(v));
    return r;
}

static __device__ __forceinline__ void mma_tf32(float c[4], const uint32_t a[4],
                                                uint32_t b0, uint32_t b1) {
    asm volatile(
        "mma.sync.aligned.m16n8k8.row.col.f32.tf32.tf32.f32 "
        "{%0,%1,%2,%3}, {%4,%5,%6,%7}, {%8,%9}, {%0,%1,%2,%3};"
        : "+f"(c[0]), "+f"(c[1]), "+f"(c[2]), "+f"(c[3])
        : "r"(a[0]), "r"(a[1]), "r"(a[2]), "r"(a[3]), "r"(b0), "r"(b1));
}

// ---------------------------------------------------------------------------
// Zero counters + output
// ---------------------------------------------------------------------------
__global__ void k_zero(float* __restrict__ out) {
    int i = blockIdx.x * 256 + threadIdx.x;
    if (i < NN) g_cnt[i] = 0;
    if (i < NGR) out[i] = 0.0f;
}

// ---------------------------------------------------------------------------
// One-time weight prep: tf32-convert + swizzle into g_Wt; combined bias.
// ---------------------------------------------------------------------------
__global__ void k_wprep(const float* __restrict__ convW, const float* __restrict__ resW,
                        const float* __restrict__ convB, const float* __restrict__ resB) {
    int t = blockIdx.x * 256 + threadIdx.x;   // 32 blocks x 256 = 8192
    if (t < 64) g_bias[t] = convB[t] + resB[t];
    if (t >= 8192) return;
    int n = t >> 6, k = t & 63;               // n in [0,128), k in [0,64)
    float v = (n < 64) ? convW[k * 64 + n] : resW[k * 64 + (n - 64)];
    g_Wt[SWZ(n, k)] = f2tf32(v);
}

// ---------------------------------------------------------------------------
// Build fixed-stride adjacency (incoming edges per dst) + in-degree counts
// ---------------------------------------------------------------------------
__global__ void k_build(const int* __restrict__ ei) {
    int e = blockIdx.x * 256 + threadIdx.x;
    if (e >= EE) return;
    int s = ei[e];
    int d = ei[EE + e];
    int pos = atomicAdd(&g_cnt[d], 1);
    if (pos < MAXD) g_adj[d * MAXD + pos] = s;
}

// ---------------------------------------------------------------------------
// Encoder: X = concat(x, pos) @ enc_W + enc_b  (Y eliminated algebraically).
// ---------------------------------------------------------------------------
__global__ void k_encoder(const float* __restrict__ x, const float* __restrict__ pos,
                          const float* __restrict__ encW, const float* __restrict__ encB) {
    __shared__ float inp[64][17];   // 16 feats, pad to 17
    __shared__ float Ws[16][64];
    __shared__ float bs[64];
    int t = threadIdx.x;  // 256
    int n0 = blockIdx.x * 64;

    for (int i = t; i < 1024; i += 256) Ws[i >> 6][i & 63] = encW[i];
    if (t < 64) bs[t] = encB[t];
    for (int i = t; i < 64 * 14; i += 256) {
        int r = i / 14, f = i - r * 14;
        int node = n0 + r; if (node >= NN) node = NN - 1;
        inp[r][f] = x[node * 14 + f];
    }
    if (t < 128) {
        int r = t >> 1, f = t & 1;
        int node = n0 + r; if (node >= NN) node = NN - 1;
        inp[r][14 + f] = pos[node * 2 + f];
    }
    __syncthreads();

    int c = t & 63;
    int rq = t >> 6;  // 0..3
#pragma unroll 4
    for (int j = 0; j < 16; j++) {
        int r = rq * 16 + j;
        int node = n0 + r;
        if (node >= NN) break;
        float acc = bs[c];
#pragma unroll
        for (int f = 0; f < 16; f++) acc += inp[r][f] * Ws[f][c];
        g_X[node * 64 + c] = acc;
    }
}

// ---------------------------------------------------------------------------
// TF32 tensor-core dual GEMM. Block: 64 rows x 128 cols. 8 warps (4M x 2N).
//   g_hWph = half2( (X @ conv_W) * dinv[row] ) ;  g_base = X @ res_W + bias
// ---------------------------------------------------------------------------
__global__ void k_layer_gemm() {
    __shared__ uint32_t Xs[64 * 64];    // 16 KB
    __shared__ uint32_t Wt[128 * 64];   // 32 KB
    int t = threadIdx.x;  // 256
    int row0 = blockIdx.x * 64;

    {
        const uint4* __restrict__ src = (const uint4*)g_Wt;
        uint4* dst = (uint4*)Wt;
#pragma unroll
        for (int i = 0; i < 8; i++) dst[t + i * 256] = src[t + i * 256];
    }
#pragma unroll
    for (int i = 0; i < 16; i++) {
        int idx = t + i * 256;          // = SWZ(r, k') destination
        int r = idx >> 6, kp = idx & 63;
        int k = kp ^ ((r & 7) << 2);    // inverse swizzle (XOR involution)
        int node = row0 + r;
        if (node >= NN) node = NN - 1;
        Xs[idx] = f2tf32(g_X[node * 64 + k]);
    }
    __syncthreads();

    int lane = t & 31, w = t >> 5;
    int wm = w & 3, wn = w >> 2;
    int g = lane >> 2, tg = lane & 3;

    float acc[8][4];
#pragma unroll
    for (int nt = 0; nt < 8; nt++)
#pragma unroll
        for (int j = 0; j < 4; j++) acc[nt][j] = 0.0f;

    int rA = wm * 16 + g;
#pragma unroll
    for (int ks = 0; ks < 8; ks++) {
        int k0 = ks * 8;
        uint32_t a[4];
        a[0] = Xs[SWZ(rA, k0 + tg)];
        a[1] = Xs[SWZ(rA + 8, k0 + tg)];
        a[2] = Xs[SWZ(rA, k0 + tg + 4)];
        a[3] = Xs[SWZ(rA + 8, k0 + tg + 4)];
#pragma unroll
        for (int nt = 0; nt < 8; nt++) {
            int n = wn * 64 + nt * 8 + g;
            uint32_t b0 = Wt[SWZ(n, k0 + tg)];
            uint32_t b1 = Wt[SWZ(n, k0 + tg + 4)];
            mma_tf32(acc[nt], a, b0, b1);
        }
    }

    if (wn == 0) {
#pragma unroll
        for (int half = 0; half < 2; half++) {
            int node = row0 + rA + half * 8;
            if (node < NN) {
                float dv = rsqrtf((float)g_cnt[node] + 1.0f);
#pragma unroll
                for (int nt = 0; nt < 8; nt++) {
                    int cp = nt * 4 + tg;
                    g_hWph[node * 32 + cp] =
                        __floats2half2_rn(acc[nt][2 * half] * dv, acc[nt][2 * half + 1] * dv);
                }
            }
        }
    } else {
#pragma unroll
        for (int half = 0; half < 2; half++) {
            int node = row0 + rA + half * 8;
            if (node < NN) {
#pragma unroll
                for (int nt = 0; nt < 8; nt++) {
                    int col = nt * 8 + 2 * tg;
                    float2 v = make_float2(acc[nt][2 * half] + g_bias[col],
                                           acc[nt][2 * half + 1] + g_bias[col + 1]);
                    *(float2*)&g_base[node * 64 + col] = v;
                }
            }
        }
    }
}

// ---------------------------------------------------------------------------
// Gather-aggregate + fused update. One warp per node; 4 edge-groups x 8
// col-slices; each lane loads uint4 (8 cols, fp16) per edge. fp32 accum.
//   X = relu( dinv[n] * (sum_in hW'[src] + hW'[n]) + base[n] )
// LAST layer: fused decoder — out[batch[n]] += X[n].decW + decB.
// ---------------------------------------------------------------------------
__global__ void k_agg_update(int last, const float* __restrict__ decW,
                             const float* __restrict__ decB,
                             const int* __restrict__ batch, float* __restrict__ out) {
    int t = threadIdx.x;  // 256 = 8 warps
    int lane = t & 31;
    int n = blockIdx.x * 8 + (t >> 5);
    if (n >= NN) return;

    int deg = g_cnt[n];
    if (deg > MAXD) deg = MAXD;
    int eg = lane >> 3;        // edge-group 0..3
    int c8 = lane & 7;         // col-slice: cols c8*8 .. c8*8+7

    const uint4* __restrict__ hw4 = (const uint4*)g_hWph;  // row stride 8 uint4

    float acc[8];
#pragma unroll
    for (int j = 0; j < 8; j++) acc[j] = 0.0f;

    // self-loop (group 0 only)
    if (eg == 0) {
        uint4 h = hw4[n * 8 + c8];
        float2 f0 = __half22float2(*(__half2*)&h.x);
        float2 f1 = __half22float2(*(__half2*)&h.y);
        float2 f2 = __half22float2(*(__half2*)&h.z);
        float2 f3 = __half22float2(*(__half2*)&h.w);
        acc[0] = f0.x; acc[1] = f0.y; acc[2] = f1.x; acc[3] = f1.y;
        acc[4] = f2.x; acc[5] = f2.y; acc[6] = f3.x; acc[7] = f3.y;
    }

    const int* __restrict__ row = &g_adj[n * MAXD];
    for (int b = 0; b < deg; b += 4) {
        if (b + eg < deg) {
            int s = row[b + eg];
            uint4 h = hw4[s * 8 + c8];
            float2 f0 = __half22float2(*(__half2*)&h.x);
            float2 f1 = __half22float2(*(__half2*)&h.y);
            float2 f2 = __half22float2(*(__half2*)&h.z);
            float2 f3 = __half22float2(*(__half2*)&h.w);
            acc[0] += f0.x; acc[1] += f0.y; acc[2] += f1.x; acc[3] += f1.y;
            acc[4] += f2.x; acc[5] += f2.y; acc[6] += f3.x; acc[7] += f3.y;
        }
    }

    // fold the 4 edge-groups (lanes differing in bits 3,4 share c8)
#pragma unroll
    for (int j = 0; j < 8; j++) {
        acc[j] += __shfl_xor_sync(0xffffffffu, acc[j], 8);
        acc[j] += __shfl_xor_sync(0xffffffffu, acc[j], 16);
    }

    if (lane < 8) {
        float dv = rsqrtf((float)g_cnt[n] + 1.0f);
        float4 b0 = *(const float4*)&g_base[n * 64 + c8 * 8];
        float4 b1 = *(const float4*)&g_base[n * 64 + c8 * 8 + 4];
        float xv[8];
        xv[0] = fmaxf(fmaf(acc[0], dv, b0.x), 0.0f);
        xv[1] = fmaxf(fmaf(acc[1], dv, b0.y), 0.0f);
        xv[2] = fmaxf(fmaf(acc[2], dv, b0.z), 0.0f);
        xv[3] = fmaxf(fmaf(acc[3], dv, b0.w), 0.0f);
        xv[4] = fmaxf(fmaf(acc[4], dv, b1.x), 0.0f);
        xv[5] = fmaxf(fmaf(acc[5], dv, b1.y), 0.0f);
        xv[6] = fmaxf(fmaf(acc[6], dv, b1.z), 0.0f);
        xv[7] = fmaxf(fmaf(acc[7], dv, b1.w), 0.0f);
        if (!last) {
            *(float4*)&g_X[n * 64 + c8 * 8] = make_float4(xv[0], xv[1], xv[2], xv[3]);
            *(float4*)&g_X[n * 64 + c8 * 8 + 4] = make_float4(xv[4], xv[5], xv[6], xv[7]);
        } else {
            float v = 0.0f;
#pragma unroll
            for (int j = 0; j < 8; j++) v += xv[j] * decW[c8 * 8 + j];
            v += __shfl_xor_sync(0x000000ffu, v, 1);
            v += __shfl_xor_sync(0x000000ffu, v, 2);
            v += __shfl_xor_sync(0x000000ffu, v, 4);
            if (lane == 0) atomicAdd(&out[batch[n]], v + decB[0]);
        }
    }
}

// ---------------------------------------------------------------------------
extern "C" void kernel_launch(void* const* d_in, const int* in_sizes, int n_in,
                              void* d_out, int out_size) {
    const float* x     = (const float*)d_in[0];
    const float* pos   = (const float*)d_in[1];
    const int*   ei    = (const int*)d_in[2];
    const int*   batch = (const int*)d_in[3];
    const float* encW  = (const float*)d_in[4];
    const float* encB  = (const float*)d_in[5];
    const float* convW = (const float*)d_in[6];
    const float* convB = (const float*)d_in[7];
    const float* resW  = (const float*)d_in[8];
    const float* resB  = (const float*)d_in[9];
    const float* decW  = (const float*)d_in[10];
    const float* decB  = (const float*)d_in[11];
    float* out         = (float*)d_out;

    const int nb_n   = (NN + 255) / 256;
    const int nb_e   = (EE + 255) / 256;
    const int nb_64  = (NN + 63) / 64;
    const int nb_agg = (NN + 7) / 8;

    k_zero<<<nb_n, 256>>>(out);
    k_wprep<<<32, 256>>>(convW, resW, convB, resB);
    k_build<<<nb_e, 256>>>(ei);
    k_encoder<<<nb_64, 256>>>(x, pos, encW, encB);

    for (int layer = 0; layer < 5; layer++) {
        k_layer_gemm<<<nb_64, 256>>>();
        k_agg_update<<<nb_agg, 256>>>(layer == 4 ? 1 : 0, decW, decB, batch, out);
    }
}

// round 16
// speedup vs baseline: 2.5239x; 1.0405x over previous
#include <cuda_runtime.h>
#include <cuda_fp16.h>
#include <cstdint>

// Problem constants
#define NN 50000
#define EE 800000
#define NH 64
#define NGR 500
#define MAXD 96   // adjacency slot stride (Poisson(16); P(deg>96) ~ 0)

// Scratch (device globals; no allocation allowed)
__device__ __align__(16) float   g_X[NN * NH];
__device__ __align__(16) __half2 g_hWph[NN * 32];  // (X @ conv_W) * dinv[row], fp16 pairs
__device__ __align__(16) float   g_base[NN * NH];  // X @ res_W + conv_b + res_b
__device__ int g_cnt[NN];
__device__ int g_adj[NN * MAXD];
__device__ __align__(16) uint32_t g_Wt[128 * 64];  // swizzled tf32 [n][k] (conv|res)
__device__ float g_bias[64];                       // convB + resB

// XOR swizzle: row-major [r][k], stride 64, k XOR'd by (r&7)*4 -> conflict-free
// for the tf32 mma fragment access pattern (lane = 4*g + tg; k=tg(+4), r/n=g).
#define SWZ(r, k) (((r) << 6) | ((k) ^ (((r) & 7) << 2)))

static __device__ __forceinline__ uint32_t f2tf32(float v) {
    uint32_t r;
    asm("cvt.rna.tf32.f32 %0, %1;" : "=r"(r) : "f"(v));
    return r;
}

static __device__ __forceinline__ void mma_tf32(float c[4], const uint32_t a[4],
                                                uint32_t b0, uint32_t b1) {
    asm volatile(
        "mma.sync.aligned.m16n8k8.row.col.f32.tf32.tf32.f32 "
        "{%0,%1,%2,%3}, {%4,%5,%6,%7}, {%8,%9}, {%0,%1,%2,%3};"
        : "+f"(c[0]), "+f"(c[1]), "+f"(c[2]), "+f"(c[3])
        : "r"(a[0]), "r"(a[1]), "r"(a[2]), "r"(a[3]), "r"(b0), "r"(b1));
}

// ---------------------------------------------------------------------------
// Fused prep: zero counters/output + weight tf32-swizzle + combined bias
// ---------------------------------------------------------------------------
__global__ void k_prep(float* __restrict__ out,
                       const float* __restrict__ convW, const float* __restrict__ resW,
                       const float* __restrict__ convB, const float* __restrict__ resB) {
    int i = blockIdx.x * 256 + threadIdx.x;
    if (i < NN) g_cnt[i] = 0;
    if (i < NGR) out[i] = 0.0f;
    if (i < 64) g_bias[i] = convB[i] + resB[i];
    if (i < 8192) {
        int n = i >> 6, k = i & 63;           // n in [0,128), k in [0,64)
        float v = (n < 64) ? convW[k * 64 + n] : resW[k * 64 + (n - 64)];
        g_Wt[SWZ(n, k)] = f2tf32(v);
    }
}

// ---------------------------------------------------------------------------
// Build fixed-stride adjacency (incoming edges per dst) + in-degree counts
// ---------------------------------------------------------------------------
__global__ void k_build(const int* __restrict__ ei) {
    int e = blockIdx.x * 256 + threadIdx.x;
    if (e >= EE) return;
    int s = ei[e];
    int d = ei[EE + e];
    int pos = atomicAdd(&g_cnt[d], 1);
    if (pos < MAXD) g_adj[d * MAXD + pos] = s;
}

// ---------------------------------------------------------------------------
// Encoder: X = concat(x, pos) @ enc_W + enc_b  (Y eliminated algebraically).
// Weights register-cached per thread-column: inner loop = 1 bcast-LDS + 1 FFMA.
// ---------------------------------------------------------------------------
__global__ void k_encoder(const float* __restrict__ x, const float* __restrict__ pos,
                          const float* __restrict__ encW, const float* __restrict__ encB) {
    __shared__ float inp[64][17];   // 16 feats, pad to 17
    __shared__ float Ws[16][64];
    int t = threadIdx.x;  // 256
    int n0 = blockIdx.x * 64;

    for (int i = t; i < 1024; i += 256) Ws[i >> 6][i & 63] = encW[i];
    for (int i = t; i < 64 * 14; i += 256) {
        int r = i / 14, f = i - r * 14;
        int node = n0 + r; if (node >= NN) node = NN - 1;
        inp[r][f] = x[node * 14 + f];
    }
    if (t < 128) {
        int r = t >> 1, f = t & 1;
        int node = n0 + r; if (node >= NN) node = NN - 1;
        inp[r][14 + f] = pos[node * 2 + f];
    }
    __syncthreads();

    int c = t & 63;
    int rq = t >> 6;  // 0..3
    float wreg[16];
#pragma unroll
    for (int f = 0; f < 16; f++) wreg[f] = Ws[f][c];
    float bias = encB[c];

#pragma unroll 4
    for (int j = 0; j < 16; j++) {
        int r = rq * 16 + j;
        int node = n0 + r;
        if (node >= NN) break;
        float acc = bias;
#pragma unroll
        for (int f = 0; f < 16; f++) acc += inp[r][f] * wreg[f];
        g_X[node * 64 + c] = acc;
    }
}

// ---------------------------------------------------------------------------
// TF32 tensor-core dual GEMM. Block: 64 rows x 128 cols. 8 warps (4M x 2N).
//   g_hWph = half2( (X @ conv_W) * dinv[row] ) ;  g_base = X @ res_W + bias
// ---------------------------------------------------------------------------
__global__ void k_layer_gemm() {
    __shared__ uint32_t Xs[64 * 64];    // 16 KB
    __shared__ uint32_t Wt[128 * 64];   // 32 KB
    int t = threadIdx.x;  // 256
    int row0 = blockIdx.x * 64;

    {
        const uint4* __restrict__ src = (const uint4*)g_Wt;
        uint4* dst = (uint4*)Wt;
#pragma unroll
        for (int i = 0; i < 8; i++) dst[t + i * 256] = src[t + i * 256];
    }
#pragma unroll
    for (int i = 0; i < 16; i++) {
        int idx = t + i * 256;          // = SWZ(r, k') destination
        int r = idx >> 6, kp = idx & 63;
        int k = kp ^ ((r & 7) << 2);    // inverse swizzle (XOR involution)
        int node = row0 + r;
        if (node >= NN) node = NN - 1;
        Xs[idx] = f2tf32(g_X[node * 64 + k]);
    }
    __syncthreads();

    int lane = t & 31, w = t >> 5;
    int wm = w & 3, wn = w >> 2;
    int g = lane >> 2, tg = lane & 3;

    float acc[8][4];
#pragma unroll
    for (int nt = 0; nt < 8; nt++)
#pragma unroll
        for (int j = 0; j < 4; j++) acc[nt][j] = 0.0f;

    int rA = wm * 16 + g;
#pragma unroll
    for (int ks = 0; ks < 8; ks++) {
        int k0 = ks * 8;
        uint32_t a[4];
        a[0] = Xs[SWZ(rA, k0 + tg)];
        a[1] = Xs[SWZ(rA + 8, k0 + tg)];
        a[2] = Xs[SWZ(rA, k0 + tg + 4)];
        a[3] = Xs[SWZ(rA + 8, k0 + tg + 4)];
#pragma unroll
        for (int nt = 0; nt < 8; nt++) {
            int n = wn * 64 + nt * 8 + g;
            uint32_t b0 = Wt[SWZ(n, k0 + tg)];
            uint32_t b1 = Wt[SWZ(n, k0 + tg + 4)];
            mma_tf32(acc[nt], a, b0, b1);
        }
    }

    if (wn == 0) {
#pragma unroll
        for (int half = 0; half < 2; half++) {
            int node = row0 + rA + half * 8;
            if (node < NN) {
                float dv = rsqrtf((float)g_cnt[node] + 1.0f);
#pragma unroll
                for (int nt = 0; nt < 8; nt++) {
                    int cp = nt * 4 + tg;
                    g_hWph[node * 32 + cp] =
                        __floats2half2_rn(acc[nt][2 * half] * dv, acc[nt][2 * half + 1] * dv);
                }
            }
        }
    } else {
#pragma unroll
        for (int half = 0; half < 2; half++) {
            int node = row0 + rA + half * 8;
            if (node < NN) {
#pragma unroll
                for (int nt = 0; nt < 8; nt++) {
                    int col = nt * 8 + 2 * tg;
                    float2 v = make_float2(acc[nt][2 * half] + g_bias[col],
                                           acc[nt][2 * half + 1] + g_bias[col + 1]);
                    *(float2*)&g_base[node * 64 + col] = v;
                }
            }
        }
    }
}

// ---------------------------------------------------------------------------
// Gather-aggregate + fused update. One warp per node; 4 edge-groups x 8
// col-slices; 8 edges/iteration (2 unconditional uint4 loads in flight/lane).
//   X = relu( dinv[n] * (sum_in hW'[src] + hW'[n]) + base[n] )
// LAST layer: fused decoder — out[batch[n]] += X[n].decW + decB.
// ---------------------------------------------------------------------------
__global__ void k_agg_update(int last, const float* __restrict__ decW,
                             const float* __restrict__ decB,
                             const int* __restrict__ batch, float* __restrict__ out) {
    int t = threadIdx.x;  // 256 = 8 warps
    int lane = t & 31;
    int n = blockIdx.x * 8 + (t >> 5);
    if (n >= NN) return;

    int deg = g_cnt[n];
    if (deg > MAXD) deg = MAXD;
    int eg = lane >> 3;        // edge-group 0..3
    int c8 = lane & 7;         // col-slice: cols c8*8 .. c8*8+7

    const uint4* __restrict__ hw4 = (const uint4*)g_hWph;  // row stride 8 uint4

    float acc[8];
#pragma unroll
    for (int j = 0; j < 8; j++) acc[j] = 0.0f;

    // self-loop (group 0 only)
    if (eg == 0) {
        uint4 h = hw4[n * 8 + c8];
        float2 f0 = __half22float2(*(__half2*)&h.x);
        float2 f1 = __half22float2(*(__half2*)&h.y);
        float2 f2 = __half22float2(*(__half2*)&h.z);
        float2 f3 = __half22float2(*(__half2*)&h.w);
        acc[0] = f0.x; acc[1] = f0.y; acc[2] = f1.x; acc[3] = f1.y;
        acc[4] = f2.x; acc[5] = f2.y; acc[6] = f3.x; acc[7] = f3.y;
    }

    const int* __restrict__ row = &g_adj[n * MAXD];
    for (int b = 0; b < deg; b += 8) {
        int i0 = b + eg, i1 = b + eg + 4;
        bool v0 = i0 < deg, v1 = i1 < deg;
        // Unconditional loads (clamped index) keep both in flight.
        int s0 = v0 ? row[i0] : n;
        int s1 = v1 ? row[i1] : n;
        uint4 h0 = hw4[s0 * 8 + c8];
        uint4 h1 = hw4[s1 * 8 + c8];
        if (v0) {
            float2 f0 = __half22float2(*(__half2*)&h0.x);
            float2 f1 = __half22float2(*(__half2*)&h0.y);
            float2 f2 = __half22float2(*(__half2*)&h0.z);
            float2 f3 = __half22float2(*(__half2*)&h0.w);
            acc[0] += f0.x; acc[1] += f0.y; acc[2] += f1.x; acc[3] += f1.y;
            acc[4] += f2.x; acc[5] += f2.y; acc[6] += f3.x; acc[7] += f3.y;
        }
        if (v1) {
            float2 f0 = __half22float2(*(__half2*)&h1.x);
            float2 f1 = __half22float2(*(__half2*)&h1.y);
            float2 f2 = __half22float2(*(__half2*)&h1.z);
            float2 f3 = __half22float2(*(__half2*)&h1.w);
            acc[0] += f0.x; acc[1] += f0.y; acc[2] += f1.x; acc[3] += f1.y;
            acc[4] += f2.x; acc[5] += f2.y; acc[6] += f3.x; acc[7] += f3.y;
        }
    }

    // fold the 4 edge-groups (lanes differing in bits 3,4 share c8)
#pragma unroll
    for (int j = 0; j < 8; j++) {
        acc[j] += __shfl_xor_sync(0xffffffffu, acc[j], 8);
        acc[j] += __shfl_xor_sync(0xffffffffu, acc[j], 16);
    }

    if (lane < 8) {
        float dv = rsqrtf((float)g_cnt[n] + 1.0f);
        float4 b0 = *(const float4*)&g_base[n * 64 + c8 * 8];
        float4 b1 = *(const float4*)&g_base[n * 64 + c8 * 8 + 4];
        float xv[8];
        xv[0] = fmaxf(fmaf(acc[0], dv, b0.x), 0.0f);
        xv[1] = fmaxf(fmaf(acc[1], dv, b0.y), 0.0f);
        xv[2] = fmaxf(fmaf(acc[2], dv, b0.z), 0.0f);
        xv[3] = fmaxf(fmaf(acc[3], dv, b0.w), 0.0f);
        xv[4] = fmaxf(fmaf(acc[4], dv, b1.x), 0.0f);
        xv[5] = fmaxf(fmaf(acc[5], dv, b1.y), 0.0f);
        xv[6] = fmaxf(fmaf(acc[6], dv, b1.z), 0.0f);
        xv[7] = fmaxf(fmaf(acc[7], dv, b1.w), 0.0f);
        if (!last) {
            *(float4*)&g_X[n * 64 + c8 * 8] = make_float4(xv[0], xv[1], xv[2], xv[3]);
            *(float4*)&g_X[n * 64 + c8 * 8 + 4] = make_float4(xv[4], xv[5], xv[6], xv[7]);
        } else {
            float v = 0.0f;
#pragma unroll
            for (int j = 0; j < 8; j++) v += xv[j] * decW[c8 * 8 + j];
            v += __shfl_xor_sync(0x000000ffu, v, 1);
            v += __shfl_xor_sync(0x000000ffu, v, 2);
            v += __shfl_xor_sync(0x000000ffu, v, 4);
            if (lane == 0) atomicAdd(&out[batch[n]], v + decB[0]);
        }
    }
}

// ---------------------------------------------------------------------------
extern "C" void kernel_launch(void* const* d_in, const int* in_sizes, int n_in,
                              void* d_out, int out_size) {
    const float* x     = (const float*)d_in[0];
    const float* pos   = (const float*)d_in[1];
    const int*   ei    = (const int*)d_in[2];
    const int*   batch = (const int*)d_in[3];
    const float* encW  = (const float*)d_in[4];
    const float* encB  = (const float*)d_in[5];
    const float* convW = (const float*)d_in[6];
    const float* convB = (const float*)d_in[7];
    const float* resW  = (const float*)d_in[8];
    const float* resB  = (const float*)d_in[9];
    const float* decW  = (const float*)d_in[10];
    const float* decB  = (const float*)d_in[11];
    float* out         = (float*)d_out;

    const int nb_n   = (NN + 255) / 256;
    const int nb_e   = (EE + 255) / 256;
    const int nb_64  = (NN + 63) / 64;
    const int nb_agg = (NN + 7) / 8;

    k_prep<<<nb_n, 256>>>(out, convW, resW, convB, resB);
    k_build<<<nb_e, 256>>>(ei);
    k_encoder<<<nb_64, 256>>>(x, pos, encW, encB);

    for (int layer = 0; layer < 5; layer++) {
        k_layer_gemm<<<nb_64, 256>>>();
        k_agg_update<<<nb_agg, 256>>>(layer == 4 ? 1 : 0, decW, decB, batch, out);
    }
}